// round 1
// baseline (speedup 1.0000x reference)
#include <cuda_runtime.h>
#include <cstdint>

// Problem constants (fixed by the dataset)
#define BATCH 4
#define SEQ   4096
#define DMODEL 4096
#define GROUPS 8
#define RANK  3
#define DG    (DMODEL / GROUPS)          // 512
#define SCALING 2.0f                     // 6.0 / 3.0
#define EPS 1e-6f

// Total elements and float4 count
#define NELEM ((long long)BATCH * SEQ * DMODEL)   // 67,108,864
#define N4    (NELEM / 4)                         // 16,777,216
#define V_PER_ROW (DMODEL / 4)                    // 1024 float4 per d-row
#define V_PER_GROUP (DG / 4)                      // 128 float4 per group

__global__ __launch_bounds__(256, 8)
void nora_rational_kernel(
    const float4* __restrict__ x,
    float4* __restrict__ out,
    const float* __restrict__ base_num,   // [G,6]
    const float* __restrict__ base_den,   // [G,4]
    const float* __restrict__ lA_num,     // [R,6]
    const float* __restrict__ lB_num,     // [G,R]
    const float* __restrict__ lA_den,     // [R,4]
    const float* __restrict__ lB_den)     // [G,R]
{
    __shared__ float s_num[GROUPS][6];
    __shared__ float s_den[GROUPS][4];

    const int t = threadIdx.x;

    // Fuse LoRA into coefficients: 48 numerator entries + 32 denominator entries.
    if (t < GROUPS * 6) {
        int g = t / 6, k = t % 6;
        float acc = base_num[t];
        #pragma unroll
        for (int r = 0; r < RANK; ++r)
            acc = fmaf(lB_num[g * RANK + r] * SCALING, lA_num[r * 6 + k], acc);
        s_num[g][k] = acc;
    } else if (t < GROUPS * 6 + GROUPS * 4) {
        int u = t - GROUPS * 6;
        int g = u / 4, k = u % 4;
        float acc = base_den[u];
        #pragma unroll
        for (int r = 0; r < RANK; ++r)
            acc = fmaf(lB_den[g * RANK + r] * SCALING, lA_den[r * 4 + k], acc);
        s_den[g][k] = acc + EPS;
    }
    __syncthreads();

    long long i = (long long)blockIdx.x * blockDim.x + t;
    if (i >= N4) return;

    // group index: position within the d-row, divided by group width.
    // V_PER_ROW = 1024 (power of two) -> cheap mask; warp-uniform group.
    int vi = (int)(i & (V_PER_ROW - 1));
    int g  = vi / V_PER_GROUP;   // vi >> 7

    const float a0 = s_num[g][0], a1 = s_num[g][1], a2 = s_num[g][2];
    const float a3 = s_num[g][3], a4 = s_num[g][4], a5 = s_num[g][5];
    const float b0 = s_den[g][0], b1 = s_den[g][1], b2 = s_den[g][2];
    const float b3 = s_den[g][3];

    float4 xv = x[i];
    float4 ov;

    #pragma unroll
    for (int lane = 0; lane < 4; ++lane) {
        float xx = (lane == 0) ? xv.x : (lane == 1) ? xv.y : (lane == 2) ? xv.z : xv.w;
        // P(x) = a0 + a1 x + ... + a5 x^5  (Horner)
        float p = fmaf(a5, xx, a4);
        p = fmaf(p, xx, a3);
        p = fmaf(p, xx, a2);
        p = fmaf(p, xx, a1);
        p = fmaf(p, xx, a0);
        // Q(x) = 1 + |b0 x + b1 x^2 + b2 x^3 + b3 x^4|
        float z = fmaf(b3, xx, b2);
        z = fmaf(z, xx, b1);
        z = fmaf(z, xx, b0);
        float q = 1.0f + fabsf(z * xx);
        float r = __fdividef(p, q);
        if (lane == 0) ov.x = r; else if (lane == 1) ov.y = r;
        else if (lane == 2) ov.z = r; else ov.w = r;
    }

    out[i] = ov;
}

extern "C" void kernel_launch(void* const* d_in, const int* in_sizes, int n_in,
                              void* d_out, int out_size)
{
    const float4* x  = (const float4*)d_in[0];
    const float* bn  = (const float*)d_in[1];
    const float* bd  = (const float*)d_in[2];
    const float* lAn = (const float*)d_in[3];
    const float* lBn = (const float*)d_in[4];
    const float* lAd = (const float*)d_in[5];
    const float* lBd = (const float*)d_in[6];
    // d_in[7] = num_groups (compile-time constant GROUPS=8)

    float4* out = (float4*)d_out;

    const int threads = 256;
    const long long blocks = (N4 + threads - 1) / threads;   // 65536

    nora_rational_kernel<<<(unsigned)blocks, threads>>>(
        x, out, bn, bd, lAn, lBn, lAd, lBd);
}

// round 2
// speedup vs baseline: 1.0800x; 1.0800x over previous
#include <cuda_runtime.h>
#include <cstdint>

// Problem constants (fixed by the dataset)
#define GROUPS 8
#define RANK  3
#define SCALING 2.0f                     // 6.0 / 3.0
#define EPS 1e-6f

#define NELEM (4LL * 4096 * 4096)        // 67,108,864
#define N4    (NELEM / 4)                // 16,777,216 float4
#define V_PER_ROW   1024                 // float4 per d-row (4096/4)
#define V_GROUP_SHIFT 7                  // 128 float4 per group

#define TPB 256
#define V_PER_THREAD 2                   // float4 per thread

__global__ __launch_bounds__(TPB, 8)
void nora_rational_kernel(
    const float4* __restrict__ x,
    float4* __restrict__ out,
    const float* __restrict__ base_num,   // [G,6]
    const float* __restrict__ base_den,   // [G,4]
    const float* __restrict__ lA_num,     // [R,6]
    const float* __restrict__ lB_num,     // [G,R]
    const float* __restrict__ lA_den,     // [R,4]
    const float* __restrict__ lB_den)     // [G,R]
{
    __shared__ float s_num[GROUPS][6];
    __shared__ float s_den[GROUPS][4];

    const int t = threadIdx.x;

    // Fuse LoRA into coefficients (80 scalar results, done by first 80 threads).
    if (t < GROUPS * 6) {
        int g = t / 6, k = t % 6;
        float acc = base_num[t];
        #pragma unroll
        for (int r = 0; r < RANK; ++r)
            acc = fmaf(lB_num[g * RANK + r] * SCALING, lA_num[r * 6 + k], acc);
        s_num[g][k] = acc;
    } else if (t < GROUPS * 6 + GROUPS * 4) {
        int u = t - GROUPS * 6;
        int g = u / 4, k = u % 4;
        float acc = base_den[u];
        #pragma unroll
        for (int r = 0; r < RANK; ++r)
            acc = fmaf(lB_den[g * RANK + r] * SCALING, lA_den[r * 4 + k], acc);
        s_den[g][k] = acc + EPS;
    }
    __syncthreads();

    // Two coalesced float4 per thread: i0 and i0 + TPB.
    const long long base = (long long)blockIdx.x * (TPB * V_PER_THREAD) + t;

    long long idx[V_PER_THREAD];
    float4 xv[V_PER_THREAD];

    // Front-batched streaming loads (evict-first; data is single-touch).
    #pragma unroll
    for (int j = 0; j < V_PER_THREAD; ++j) {
        idx[j] = base + (long long)j * TPB;
        xv[j]  = __ldcs(&x[idx[j]]);
    }

    #pragma unroll
    for (int j = 0; j < V_PER_THREAD; ++j) {
        int vi = (int)(idx[j] & (V_PER_ROW - 1));
        int g  = vi >> V_GROUP_SHIFT;

        const float a0 = s_num[g][0], a1 = s_num[g][1], a2 = s_num[g][2];
        const float a3 = s_num[g][3], a4 = s_num[g][4], a5 = s_num[g][5];
        const float b0 = s_den[g][0], b1 = s_den[g][1], b2 = s_den[g][2];
        const float b3 = s_den[g][3];

        float4 v = xv[j];
        float4 ov;
        #pragma unroll
        for (int lane = 0; lane < 4; ++lane) {
            float xx = (lane == 0) ? v.x : (lane == 1) ? v.y : (lane == 2) ? v.z : v.w;
            // P(x) = a0 + a1 x + ... + a5 x^5  (Horner)
            float p = fmaf(a5, xx, a4);
            p = fmaf(p, xx, a3);
            p = fmaf(p, xx, a2);
            p = fmaf(p, xx, a1);
            p = fmaf(p, xx, a0);
            // Q(x) = 1 + |b0 x + b1 x^2 + b2 x^3 + b3 x^4|
            float z = fmaf(b3, xx, b2);
            z = fmaf(z, xx, b1);
            z = fmaf(z, xx, b0);
            float q = 1.0f + fabsf(z * xx);
            float r = __fdividef(p, q);
            if (lane == 0) ov.x = r; else if (lane == 1) ov.y = r;
            else if (lane == 2) ov.z = r; else ov.w = r;
        }
        __stcs(&out[idx[j]], ov);
    }
}

extern "C" void kernel_launch(void* const* d_in, const int* in_sizes, int n_in,
                              void* d_out, int out_size)
{
    const float4* x  = (const float4*)d_in[0];
    const float* bn  = (const float*)d_in[1];
    const float* bd  = (const float*)d_in[2];
    const float* lAn = (const float*)d_in[3];
    const float* lBn = (const float*)d_in[4];
    const float* lAd = (const float*)d_in[5];
    const float* lBd = (const float*)d_in[6];

    float4* out = (float4*)d_out;

    const long long blocks = N4 / (TPB * V_PER_THREAD);   // 32768, exact

    nora_rational_kernel<<<(unsigned)blocks, TPB>>>(
        x, out, bn, bd, lAn, lBn, lAd, lBd);
}

// round 4
// speedup vs baseline: 1.0804x; 1.0004x over previous
#include <cuda_runtime.h>
#include <cstdint>

// Problem constants (fixed by the dataset)
#define GROUPS 8
#define RANK  3
#define SCALING 2.0f                     // 6.0 / 3.0
#define EPS 1e-6f

#define NELEM (4LL * 4096 * 4096)        // 67,108,864
#define N4    (NELEM / 4)                // 16,777,216 float4 (fits in int32)
#define V_PER_ROW   1024                 // float4 per d-row (4096/4)
#define V_GROUP_SHIFT 7                  // 128 float4 per group

#define TPB 256
#define V_PER_THREAD 4                   // float4 per thread (64B in flight)

__global__ __launch_bounds__(TPB, 5)
void nora_rational_kernel(
    const float4* __restrict__ x,
    float4* __restrict__ out,
    const float* __restrict__ base_num,   // [G,6]
    const float* __restrict__ base_den,   // [G,4]
    const float* __restrict__ lA_num,     // [R,6]
    const float* __restrict__ lB_num,     // [G,R]
    const float* __restrict__ lA_den,     // [R,4]
    const float* __restrict__ lB_den)     // [G,R]
{
    __shared__ float s_num[GROUPS][6];
    __shared__ float s_den[GROUPS][4];

    const int t = threadIdx.x;

    // Fuse LoRA into coefficients (80 scalar results, first 80 threads).
    if (t < GROUPS * 6) {
        int g = t / 6, k = t % 6;
        float acc = base_num[t];
        #pragma unroll
        for (int r = 0; r < RANK; ++r)
            acc = fmaf(lB_num[g * RANK + r] * SCALING, lA_num[r * 6 + k], acc);
        s_num[g][k] = acc;
    } else if (t < GROUPS * 6 + GROUPS * 4) {
        int u = t - GROUPS * 6;
        int g = u / 4, k = u % 4;
        float acc = base_den[u];
        #pragma unroll
        for (int r = 0; r < RANK; ++r)
            acc = fmaf(lB_den[g * RANK + r] * SCALING, lA_den[r * 4 + k], acc);
        s_den[g][k] = acc + EPS;
    }
    __syncthreads();

    // Four coalesced float4 per thread, all 32-bit indexing.
    const int base = blockIdx.x * (TPB * V_PER_THREAD) + t;

    float4 xv[V_PER_THREAD];

    // Front-batched streaming loads (evict-first; single-touch data).
    #pragma unroll
    for (int j = 0; j < V_PER_THREAD; ++j)
        xv[j] = __ldcs(&x[base + j * TPB]);

    #pragma unroll
    for (int j = 0; j < V_PER_THREAD; ++j) {
        const int i  = base + j * TPB;
        const int vi = i & (V_PER_ROW - 1);
        const int g  = vi >> V_GROUP_SHIFT;

        const float a0 = s_num[g][0], a1 = s_num[g][1], a2 = s_num[g][2];
        const float a3 = s_num[g][3], a4 = s_num[g][4], a5 = s_num[g][5];
        const float b0 = s_den[g][0], b1 = s_den[g][1], b2 = s_den[g][2];
        const float b3 = s_den[g][3];

        float4 v = xv[j];
        float4 ov;
        #pragma unroll
        for (int lane = 0; lane < 4; ++lane) {
            float xx = (lane == 0) ? v.x : (lane == 1) ? v.y : (lane == 2) ? v.z : v.w;
            // P(x) = a0 + a1 x + ... + a5 x^5  (Horner)
            float p = fmaf(a5, xx, a4);
            p = fmaf(p, xx, a3);
            p = fmaf(p, xx, a2);
            p = fmaf(p, xx, a1);
            p = fmaf(p, xx, a0);
            // Q(x) = 1 + |b0 x + b1 x^2 + b2 x^3 + b3 x^4|
            float z = fmaf(b3, xx, b2);
            z = fmaf(z, xx, b1);
            z = fmaf(z, xx, b0);
            float q = 1.0f + fabsf(z * xx);
            float r = __fdividef(p, q);
            if (lane == 0) ov.x = r; else if (lane == 1) ov.y = r;
            else if (lane == 2) ov.z = r; else ov.w = r;
        }
        __stcs(&out[i], ov);
    }
}

extern "C" void kernel_launch(void* const* d_in, const int* in_sizes, int n_in,
                              void* d_out, int out_size)
{
    const float4* x  = (const float4*)d_in[0];
    const float* bn  = (const float*)d_in[1];
    const float* bd  = (const float*)d_in[2];
    const float* lAn = (const float*)d_in[3];
    const float* lBn = (const float*)d_in[4];
    const float* lAd = (const float*)d_in[5];
    const float* lBd = (const float*)d_in[6];

    float4* out = (float4*)d_out;

    const int blocks = (int)(N4 / (TPB * V_PER_THREAD));   // 16384, exact

    nora_rational_kernel<<<blocks, TPB>>>(
        x, out, bn, bd, lAn, lBn, lAd, lBd);
}